// round 5
// baseline (speedup 1.0000x reference)
#include <cuda_runtime.h>
#include <cuda_fp16.h>
#include <cstdint>

#define OUTF 2048
#define INF  2048
#define SWARM 32
#define MROWS (4*4096)

// Device-global scratch (no runtime allocation allowed)
__device__ __half g_W[(size_t)OUTF * INF];   // 8 MB: sign weights, +/-1 in fp16
__device__ __half g_X[(size_t)MROWS * INF];  // 64 MB: x converted to fp16

// ---------------------------------------------------------------------------
// Kernel 1: swarm reduction.  population[(o*INF+i)*32 .. +32) -> sign -> g_W
// ---------------------------------------------------------------------------
__global__ void pop_reduce_kernel(const float* __restrict__ pop) {
    int idx = blockIdx.x * blockDim.x + threadIdx.x;
    if (idx >= OUTF * INF) return;
    const float4* p = reinterpret_cast<const float4*>(pop + (size_t)idx * SWARM);
    float s = 0.f;
#pragma unroll
    for (int j = 0; j < 8; j++) {
        float4 v = p[j];
        s += (v.x + v.y) + (v.z + v.w);
    }
    // sign with sign(0) -> +1  (sum of +/-1s is an exact integer in fp32)
    g_W[idx] = __float2half(s >= 0.f ? 1.f : -1.f);
}

// ---------------------------------------------------------------------------
// Kernel 2: x fp32 -> fp16
// ---------------------------------------------------------------------------
__global__ void conv_x_kernel(const float* __restrict__ x) {
    int idx = blockIdx.x * blockDim.x + threadIdx.x;   // one float4 per thread
    int i4 = idx * 4;
    if (i4 >= MROWS * INF) return;
    float4 v = reinterpret_cast<const float4*>(x)[idx];
    __half2* o = reinterpret_cast<__half2*>(g_X + i4);
    o[0] = __floats2half2_rn(v.x, v.y);
    o[1] = __floats2half2_rn(v.z, v.w);
}

// ---------------------------------------------------------------------------
// Kernel 3: GEMM  C[M,N] = X[M,K] * W^T   (W is [N,K], K contiguous for both)
// mma.sync.aligned.m16n8k16.row.col.f32.f16.f16.f32
// CTA tile 128x128x32, 8 warps in 4(M) x 2(N), warp tile 32x64.
// 2-stage cp.async pipeline: tile k+1 streams to smem while tile k computes.
// ---------------------------------------------------------------------------
#define BM 128
#define BN 128
#define BK 32
#define SPAD 8   // row stride 40 halves = 80 B (multiple of 16: cp.async-aligned)

__global__ __launch_bounds__(256, 2)
void gemm_hmma_kernel(float* __restrict__ C) {
    __shared__ __half As[2][BM][BK + SPAD];
    __shared__ __half Bs[2][BN][BK + SPAD];

    const int tid  = threadIdx.x;
    const int warp = tid >> 5;
    const int lane = tid & 31;
    const int warpM = warp & 3;       // 0..3 -> 32-row slab
    const int warpN = warp >> 2;      // 0..1 -> 64-col slab
    const int g   = lane >> 2;        // group id 0..7
    const int tig = lane & 3;         // thread-in-group

    const int blockM = blockIdx.y * BM;   // grid.x = N-blocks (fastest) for L2 reuse of A
    const int blockN = blockIdx.x * BN;

    const __half* __restrict__ A = g_X;
    const __half* __restrict__ B = g_W;

    float acc[2][8][4];
#pragma unroll
    for (int mi = 0; mi < 2; mi++)
#pragma unroll
        for (int ni = 0; ni < 8; ni++)
#pragma unroll
            for (int r = 0; r < 4; r++) acc[mi][ni][r] = 0.f;

    // global-load mapping: 4 threads per 32-half row, 2 passes of 64 rows
    const int lr = tid >> 2;          // 0..63
    const int lc = (tid & 3) * 8;     // 0,8,16,24

    // async tile loader: 4 x 16B cp.async per thread per tile
    auto load_tile = [&](int stage, int k0) {
#pragma unroll
        for (int p = 0; p < 2; p++) {
            int row = lr + p * 64;
            uint32_t sa = (uint32_t)__cvta_generic_to_shared(&As[stage][row][lc]);
            const void* ga = A + (size_t)(blockM + row) * INF + k0 + lc;
            asm volatile("cp.async.cg.shared.global [%0], [%1], 16;\n"
                         :: "r"(sa), "l"(ga));
            uint32_t sb = (uint32_t)__cvta_generic_to_shared(&Bs[stage][row][lc]);
            const void* gb = B + (size_t)(blockN + row) * INF + k0 + lc;
            asm volatile("cp.async.cg.shared.global [%0], [%1], 16;\n"
                         :: "r"(sb), "l"(gb));
        }
        asm volatile("cp.async.commit_group;\n");
    };

    const int KT = INF / BK;   // 64 tiles
    load_tile(0, 0);

    for (int kt = 0; kt < KT; kt++) {
        const int stage = kt & 1;
        if (kt + 1 < KT) {
            load_tile(stage ^ 1, (kt + 1) * BK);
            asm volatile("cp.async.wait_group 1;\n");
        } else {
            asm volatile("cp.async.wait_group 0;\n");
        }
        __syncthreads();

#pragma unroll
        for (int ks = 0; ks < 2; ks++) {
            const int kb = ks * 16;
            uint32_t a[2][4], b[8][2];
#pragma unroll
            for (int mi = 0; mi < 2; mi++) {
                int rb = warpM * 32 + mi * 16;
                a[mi][0] = *reinterpret_cast<const uint32_t*>(&As[stage][rb + g    ][kb + tig * 2    ]);
                a[mi][1] = *reinterpret_cast<const uint32_t*>(&As[stage][rb + g + 8][kb + tig * 2    ]);
                a[mi][2] = *reinterpret_cast<const uint32_t*>(&As[stage][rb + g    ][kb + tig * 2 + 8]);
                a[mi][3] = *reinterpret_cast<const uint32_t*>(&As[stage][rb + g + 8][kb + tig * 2 + 8]);
            }
#pragma unroll
            for (int ni = 0; ni < 8; ni++) {
                int nb = warpN * 64 + ni * 8 + g;
                b[ni][0] = *reinterpret_cast<const uint32_t*>(&Bs[stage][nb][kb + tig * 2    ]);
                b[ni][1] = *reinterpret_cast<const uint32_t*>(&Bs[stage][nb][kb + tig * 2 + 8]);
            }
#pragma unroll
            for (int mi = 0; mi < 2; mi++)
#pragma unroll
                for (int ni = 0; ni < 8; ni++) {
                    asm volatile(
                        "mma.sync.aligned.m16n8k16.row.col.f32.f16.f16.f32 "
                        "{%0,%1,%2,%3}, {%4,%5,%6,%7}, {%8,%9}, {%0,%1,%2,%3};"
                        : "+f"(acc[mi][ni][0]), "+f"(acc[mi][ni][1]),
                          "+f"(acc[mi][ni][2]), "+f"(acc[mi][ni][3])
                        : "r"(a[mi][0]), "r"(a[mi][1]), "r"(a[mi][2]), "r"(a[mi][3]),
                          "r"(b[ni][0]), "r"(b[ni][1]));
                }
        }
        __syncthreads();
    }

    // epilogue: c0,c1 -> (row g, cols tig*2,+1); c2,c3 -> (row g+8, same cols)
#pragma unroll
    for (int mi = 0; mi < 2; mi++) {
        int row0 = blockM + warpM * 32 + mi * 16 + g;
#pragma unroll
        for (int ni = 0; ni < 8; ni++) {
            int col = blockN + warpN * 64 + ni * 8 + tig * 2;
            float2 v0 = make_float2(acc[mi][ni][0], acc[mi][ni][1]);
            float2 v1 = make_float2(acc[mi][ni][2], acc[mi][ni][3]);
            *reinterpret_cast<float2*>(C + (size_t)row0 * OUTF + col)       = v0;
            *reinterpret_cast<float2*>(C + (size_t)(row0 + 8) * OUTF + col) = v1;
        }
    }
}

// ---------------------------------------------------------------------------
extern "C" void kernel_launch(void* const* d_in, const int* in_sizes, int n_in,
                              void* d_out, int out_size) {
    // metadata order: x first, population second — but disambiguate by size
    const float* x   = (const float*)d_in[0];
    const float* pop = (const float*)d_in[1];
    if (n_in >= 2 && in_sizes[0] == OUTF * INF * SWARM) {
        pop = (const float*)d_in[0];
        x   = (const float*)d_in[1];
    }
    float* out = (float*)d_out;

    {
        int n = OUTF * INF;
        pop_reduce_kernel<<<(n + 255) / 256, 256>>>(pop);
    }
    {
        int n4 = (MROWS * INF) / 4;
        conv_x_kernel<<<(n4 + 255) / 256, 256>>>(x);
    }
    {
        dim3 grid(OUTF / BN, MROWS / BM);   // x = N-blocks (fastest), y = M-blocks
        gemm_hmma_kernel<<<grid, 256>>>(out);
    }
}

// round 7
// speedup vs baseline: 1.0257x; 1.0257x over previous
#include <cuda_runtime.h>
#include <cuda_fp16.h>
#include <cstdint>

#define OUTF 2048
#define INF  2048
#define SWARM 32
#define MROWS (4*4096)

// Device-global scratch (no runtime allocation allowed)
__device__ __half g_W[(size_t)OUTF * INF];   // 8 MB: sign weights, +/-1 in fp16
__device__ __half g_X[(size_t)MROWS * INF];  // 64 MB: x converted to fp16

// ---------------------------------------------------------------------------
// Kernel 1: swarm reduction — coalesced: 8 threads per swarm row.
// Warp reads 512 contiguous bytes (4 lines) instead of 32 lines per LDG.
// ---------------------------------------------------------------------------
__global__ void pop_reduce_kernel(const float* __restrict__ pop) {
    int gt  = blockIdx.x * blockDim.x + threadIdx.x;   // one float4 per thread
    int row = gt >> 3;                                  // 8 threads per row of 32 floats
    int c   = gt & 7;
    float4 v = reinterpret_cast<const float4*>(pop)[(size_t)row * 8 + c];
    float s = (v.x + v.y) + (v.z + v.w);
    s += __shfl_xor_sync(0xFFFFFFFFu, s, 1);
    s += __shfl_xor_sync(0xFFFFFFFFu, s, 2);
    s += __shfl_xor_sync(0xFFFFFFFFu, s, 4);
    if (c == 0) g_W[row] = __float2half(s >= 0.f ? 1.f : -1.f);
}

// ---------------------------------------------------------------------------
// Kernel 2: x fp32 -> fp16
// ---------------------------------------------------------------------------
__global__ void conv_x_kernel(const float* __restrict__ x) {
    int idx = blockIdx.x * blockDim.x + threadIdx.x;   // one float4 per thread
    int i4 = idx * 4;
    if (i4 >= MROWS * INF) return;
    float4 v = reinterpret_cast<const float4*>(x)[idx];
    __half2* o = reinterpret_cast<__half2*>(g_X + i4);
    o[0] = __floats2half2_rn(v.x, v.y);
    o[1] = __floats2half2_rn(v.z, v.w);
}

// ---------------------------------------------------------------------------
// Kernel 3: GEMM  C[M,N] = X[M,K] * W^T   (W is [N,K], K contiguous for both)
// mma.sync.m16n8k16 + ldmatrix.x4 fragment loads + 3-stage cp.async pipeline.
// CTA tile 128x128x32, 8 warps 4(M) x 2(N), warp tile 32x64.
// Smem: 64B rows (BK=32 halves), XOR swizzle chunk^=(row&3): conflict-free for
// both cp.async 16B writes and ldmatrix 8x16B row reads. 16KB/stage, 3 stages.
// ---------------------------------------------------------------------------
#define BM 128
#define BN 128
#define BK 32
#define STAGE 16384        // A 8KB + B 8KB
#define NSTAGE 3

__device__ __forceinline__ uint32_t smem_u32(const void* p) {
    uint32_t a;
    asm("{ .reg .u64 t; cvta.to.shared.u64 t, %1; cvt.u32.u64 %0, t; }"
        : "=r"(a) : "l"(p));
    return a;
}

__device__ __forceinline__ void ldsm_x4(uint32_t* r, uint32_t addr) {
    asm volatile("ldmatrix.sync.aligned.m8n8.x4.shared.b16 {%0,%1,%2,%3}, [%4];"
                 : "=r"(r[0]), "=r"(r[1]), "=r"(r[2]), "=r"(r[3]) : "r"(addr));
}

__global__ __launch_bounds__(256, 2)
void gemm_hmma_kernel(float* __restrict__ C) {
    __shared__ __align__(1024) char smem[NSTAGE * STAGE];
    const uint32_t sbase = smem_u32(smem);

    const int tid  = threadIdx.x;
    const int warp = tid >> 5;
    const int lane = tid & 31;
    const int warpM = warp & 3;       // 0..3 -> 32-row slab
    const int warpN = warp >> 2;      // 0..1 -> 64-col slab
    const int g   = lane >> 2;        // group id 0..7 (epilogue)
    const int tig = lane & 3;

    // ldmatrix lane decomposition
    const int r8  = lane & 7;
    const int mh  = (lane >> 3) & 1;  // matrix-pair select bit
    const int mk  = lane >> 4;        // 0/1

    const int blockM = blockIdx.y * BM;   // grid.x = N-blocks (fastest): L2 A reuse
    const int blockN = blockIdx.x * BN;

    float acc[2][8][4];
#pragma unroll
    for (int mi = 0; mi < 2; mi++)
#pragma unroll
        for (int ni = 0; ni < 8; ni++)
#pragma unroll
            for (int r = 0; r < 4; r++) acc[mi][ni][r] = 0.f;

    // async fill of tile c into stage c%3: per thread 2 A-chunks + 2 B-chunks (16B)
    auto fill = [&](int c) {
        const int s = c % NSTAGE;
        const uint32_t ab = sbase + s * STAGE;
        const uint32_t bb = ab + 8192;
        const int k0 = c * BK;
#pragma unroll
        for (int t = 0; t < 2; t++) {
            int id  = t * 256 + tid;          // 0..511
            int row = id >> 2, ch = id & 3;
            uint32_t da = ab + row * 64 + ((ch ^ (row & 3)) << 4);
            const void* sa = g_X + (size_t)(blockM + row) * INF + k0 + ch * 8;
            asm volatile("cp.async.cg.shared.global [%0], [%1], 16;" :: "r"(da), "l"(sa));
            uint32_t db = bb + row * 64 + ((ch ^ (row & 3)) << 4);
            const void* sb = g_W + (size_t)(blockN + row) * INF + k0 + ch * 8;
            asm volatile("cp.async.cg.shared.global [%0], [%1], 16;" :: "r"(db), "l"(sb));
        }
        asm volatile("cp.async.commit_group;");
    };

    const int KT = INF / BK;   // 64 tiles
    fill(0);
    fill(1);

    for (int c = 0; c < KT; c++) {
        if (c + 1 < KT) asm volatile("cp.async.wait_group 1;");
        else            asm volatile("cp.async.wait_group 0;");
        __syncthreads();
        if (c + 2 < KT) fill(c + 2);

        const uint32_t ab = sbase + (c % NSTAGE) * STAGE;
        const uint32_t bb = ab + 8192;

#pragma unroll
        for (int ks = 0; ks < 2; ks++) {
            uint32_t a[2][4], b[4][4];
#pragma unroll
            for (int mi = 0; mi < 2; mi++) {
                int row = warpM * 32 + mi * 16 + mh * 8 + r8;
                int ch  = ks * 2 + mk;
                ldsm_x4(a[mi], ab + row * 64 + ((ch ^ (row & 3)) << 4));
            }
#pragma unroll
            for (int p = 0; p < 4; p++) {
                int row = warpN * 64 + p * 16 + mk * 8 + r8;
                int ch  = ks * 2 + mh;
                ldsm_x4(b[p], bb + row * 64 + ((ch ^ (row & 3)) << 4));
            }
#pragma unroll
            for (int mi = 0; mi < 2; mi++)
#pragma unroll
                for (int ni = 0; ni < 8; ni++) {
                    const uint32_t b0 = b[ni >> 1][(ni & 1) * 2];
                    const uint32_t b1 = b[ni >> 1][(ni & 1) * 2 + 1];
                    asm volatile(
                        "mma.sync.aligned.m16n8k16.row.col.f32.f16.f16.f32 "
                        "{%0,%1,%2,%3}, {%4,%5,%6,%7}, {%8,%9}, {%0,%1,%2,%3};"
                        : "+f"(acc[mi][ni][0]), "+f"(acc[mi][ni][1]),
                          "+f"(acc[mi][ni][2]), "+f"(acc[mi][ni][3])
                        : "r"(a[mi][0]), "r"(a[mi][1]), "r"(a[mi][2]), "r"(a[mi][3]),
                          "r"(b0), "r"(b1));
                }
        }
    }

    // epilogue: c0,c1 -> (row g, cols tig*2,+1); c2,c3 -> (row g+8, same cols)
#pragma unroll
    for (int mi = 0; mi < 2; mi++) {
        int row0 = blockM + warpM * 32 + mi * 16 + g;
#pragma unroll
        for (int ni = 0; ni < 8; ni++) {
            int col = blockN + warpN * 64 + ni * 8 + tig * 2;
            float2 v0 = make_float2(acc[mi][ni][0], acc[mi][ni][1]);
            float2 v1 = make_float2(acc[mi][ni][2], acc[mi][ni][3]);
            *reinterpret_cast<float2*>(C + (size_t)row0 * OUTF + col)       = v0;
            *reinterpret_cast<float2*>(C + (size_t)(row0 + 8) * OUTF + col) = v1;
        }
    }
}

// ---------------------------------------------------------------------------
extern "C" void kernel_launch(void* const* d_in, const int* in_sizes, int n_in,
                              void* d_out, int out_size) {
    const float* x   = (const float*)d_in[0];
    const float* pop = (const float*)d_in[1];
    if (n_in >= 2 && in_sizes[0] == OUTF * INF * SWARM) {
        pop = (const float*)d_in[0];
        x   = (const float*)d_in[1];
    }
    float* out = (float*)d_out;

    {
        int nthreads = OUTF * INF * 8;   // 8 threads per swarm row
        pop_reduce_kernel<<<nthreads / 256, 256>>>(pop);
    }
    {
        int n4 = (MROWS * INF) / 4;
        conv_x_kernel<<<(n4 + 255) / 256, 256>>>(x);
    }
    {
        dim3 grid(OUTF / BN, MROWS / BM);   // x = N-blocks (fastest), y = M-blocks
        gemm_hmma_kernel<<<grid, 256>>>(out);
    }
}